// round 4
// baseline (speedup 1.0000x reference)
#include <cuda_runtime.h>

#define KTOP 512
#define NBL 16
#define NANCH 65280
#define NB2 3072          // fine bins (2868 used)
#define CAND 1024
#define KBASE 0xBE19999Au // fkey(0.15f)
#define KSHIFT 13

__device__ unsigned g_key[4 * NANCH];
__device__ float4   g_box[4 * NANCH];
__device__ float    g_sc [4 * NANCH];
__device__ int      g_lab[4 * NANCH];
__device__ unsigned g_hist[NBL * NB2];
__device__ float4   g_tbox[NBL * KTOP];
__device__ float    g_tsc [NBL * KTOP];
__device__ int      g_tlab[NBL * KTOP];
__device__ unsigned g_tval[NBL * 16];
__device__ unsigned g_mask[NBL * KTOP * 16];

__constant__ int   c_HW[4]  = {16384, 4096, 1024, 256};
__constant__ int   c_lg[4]  = {14, 12, 10, 8};
__constant__ int   c_N[4]   = {49152, 12288, 3072, 768};
__constant__ int   c_off[4] = {0, 49152, 61440, 64512};
__constant__ float c_fs[4]  = {0.25f, 0.125f, 0.0625f, 0.03125f};
__constant__ float c_wsc[4] = {0.8f, 0.9f, 1.0f, 1.1f};
__constant__ float c_hsc[4] = {1.0f, 1.2f, 1.4f, 1.6f};
__constant__ float c_ew[4]  = {0.2f, 0.3f, 0.4f, 0.5f};
__constant__ float c_eh[4]  = {0.4f, 0.6f, 0.8f, 1.0f};
__constant__ float c_pwl[4] = {0.008f, 0.016f, 0.024f, 0.032f};
__constant__ float c_pwh[4] = {0.054f, 0.072f, 0.09f, 0.108f};
__constant__ float c_phl[4] = {0.008f, 0.016f, 0.024f, 0.032f};
__constant__ float c_phh[4] = {0.072f, 0.096f, 0.12f, 0.144f};
__constant__ float c_whl[4] = {0.005f, 0.01f, 0.015f, 0.02f};
__constant__ float c_whh[4] = {0.12f, 0.16f, 0.2f, 0.24f};

__device__ __forceinline__ unsigned fkey(float f) {
    unsigned u = __float_as_uint(f);
    return u ^ ((u >> 31) ? 0xFFFFFFFFu : 0x80000000u);
}

// XLA tanh: rational approximation, separate mul/add (no FMA contraction).
__device__ __forceinline__ float xla_tanh(float x) {
    float xc = fminf(fmaxf(x, -9.0f), 9.0f);
    float x2 = __fmul_rn(xc, xc);
    float p = -2.76076847742355e-16f;
    p = __fadd_rn(__fmul_rn(p, x2), 2.00018790482477e-13f);
    p = __fadd_rn(__fmul_rn(p, x2), -8.60467152213735e-11f);
    p = __fadd_rn(__fmul_rn(p, x2), 5.12229709037114e-08f);
    p = __fadd_rn(__fmul_rn(p, x2), 1.48572235717979e-05f);
    p = __fadd_rn(__fmul_rn(p, x2), 6.37261928875436e-04f);
    p = __fadd_rn(__fmul_rn(p, x2), 4.89352455891786e-03f);
    p = __fmul_rn(xc, p);
    float q = 1.19825839466702e-06f;
    q = __fadd_rn(__fmul_rn(q, x2), 1.18534705686654e-04f);
    q = __fadd_rn(__fmul_rn(q, x2), 2.26843463243900e-03f);
    q = __fadd_rn(__fmul_rn(q, x2), 4.89352518554385e-03f);
    float r = __fdiv_rn(p, q);
    return (fabsf(x) < 0.0004f) ? x : r;
}
__device__ __forceinline__ float xla_sigmoid(float x) {
    return __fadd_rn(0.5f, __fmul_rn(0.5f, xla_tanh(__fmul_rn(0.5f, x))));
}
__device__ __forceinline__ float clip01(float x) { return fminf(fmaxf(x, 0.0f), 1.0f); }

__global__ void __launch_bounds__(256) decode_kernel(
    const float* __restrict__ cls0, const float* __restrict__ box0, const float* __restrict__ anc0,
    const float* __restrict__ cls1, const float* __restrict__ box1, const float* __restrict__ anc1,
    const float* __restrict__ cls2, const float* __restrict__ box2, const float* __restrict__ anc2,
    const float* __restrict__ cls3, const float* __restrict__ box3, const float* __restrict__ anc3)
{
    int l = blockIdx.z, b = blockIdx.y;
    int i = blockIdx.x * 256 + threadIdx.x;
    if (i >= c_N[l]) return;
    int HW = c_HW[l], lg = c_lg[l];
    const float* cls = (l == 0) ? cls0 : (l == 1) ? cls1 : (l == 2) ? cls2 : cls3;
    const float* box = (l == 0) ? box0 : (l == 1) ? box1 : (l == 2) ? box2 : box3;
    const float* anc = (l == 0) ? anc0 : (l == 1) ? anc1 : (l == 2) ? anc2 : anc3;

    int a = i >> lg, p = i & (HW - 1);
    const float* cb = cls + (size_t)((b * 3 + a) * 3) * HW + p;
    float s0 = xla_sigmoid(cb[0]);
    float s1 = xla_sigmoid(cb[HW]);
    float s2 = xla_sigmoid(cb[2 * HW]);
    float ms = s0; int lb = 0;
    if (s1 > ms) { ms = s1; lb = 1; }
    if (s2 > ms) { ms = s2; lb = 2; }

    const float* db = box + (size_t)((b * 3 + a) * 4) * HW + p;
    float d0 = db[0], d1 = db[HW], d2 = db[2 * HW], d3 = db[3 * HW];

    float4 A = ((const float4*)anc)[i];
    const float inv = 0.001953125f;
    float aw  = __fmul_rn(__fsub_rn(A.z, A.x), inv);
    float ah  = __fmul_rn(__fsub_rn(A.w, A.y), inv);
    float acx = __fmul_rn(__fmul_rn(__fadd_rn(A.x, A.z), 0.5f), inv);
    float acy = __fmul_rn(__fmul_rn(__fadd_rn(A.y, A.w), 0.5f), inv);

    float dx = __fmul_rn(__fmul_rn(fminf(fmaxf(__fmul_rn(d0, 0.2f), -1.0f), 1.0f), c_fs[l]), aw);
    float dy = __fmul_rn(__fmul_rn(fminf(fmaxf(__fmul_rn(d1, 0.2f), -1.0f), 1.0f), c_fs[l]), ah);
    float cx = clip01(__fadd_rn(acx, dx));
    float cy = clip01(__fadd_rn(acy, dy));
    float dw = fminf(fmaxf(__fmul_rn(d2, 0.2f), -2.0f), 2.0f);
    float dh = fminf(fmaxf(__fmul_rn(d3, 0.2f), -2.0f), 2.0f);
    float pw = fminf(fmaxf(__fmul_rn(__fmul_rn(aw, c_wsc[l]), expf(__fmul_rn(dw, c_ew[l]))), c_pwl[l]), c_pwh[l]);
    float ph = fminf(fmaxf(__fmul_rn(__fmul_rn(ah, c_hsc[l]), expf(__fmul_rn(dh, c_eh[l]))), c_phl[l]), c_phh[l]);

    float x0 = clip01(__fsub_rn(cx, __fmul_rn(0.5f, pw)));
    float y0 = clip01(__fsub_rn(cy, __fmul_rn(0.5f, ph)));
    float x1 = clip01(__fadd_rn(cx, __fmul_rn(0.5f, pw)));
    float y1 = clip01(__fadd_rn(cy, __fmul_rn(0.5f, ph)));
    float w = __fsub_rn(x1, x0);
    float h = __fsub_rn(y1, y0);

    bool valid = (ms > 0.15f) && (w > c_whl[l]) && (h > c_whl[l]) && (w < c_whh[l]) && (h < c_whh[l]);
    int off = b * NANCH + c_off[l] + i;
    g_box[off] = make_float4(x0, y0, x1, y1);
    g_sc[off]  = ms;
    g_lab[off] = lb;
    unsigned key = valid ? fkey(ms) : 0u;
    g_key[off] = key;
    if (valid) atomicAdd(&g_hist[(b * 4 + l) * NB2 + ((key - KBASE) >> KSHIFT)], 1u);
}

__global__ void __launch_bounds__(512) topk_kernel() {
    __shared__ unsigned sH[NB2];
    __shared__ unsigned sSuf[513];
    __shared__ unsigned sWSum[16];
    __shared__ unsigned long long sCand[CAND];
    __shared__ unsigned sThr, sCtr;
    __shared__ int sChunk;
    int bl = blockIdx.x, b = bl >> 2, l = bl & 3;
    int t = threadIdx.x, lane = t & 31, wp = t >> 5;
    int N = c_N[l];
    int off = b * NANCH + c_off[l];
    unsigned* hist = g_hist + bl * NB2;

    // hist -> smem, then zero gmem for next replay
    for (int i = t; i < NB2; i += 512) { sH[i] = hist[i]; }
    __syncthreads();
    for (int i = t; i < NB2; i += 512) hist[i] = 0u;

    // chunk sums: 512 chunks of 6 bins
    unsigned s = 0;
    #pragma unroll
    for (int j = 0; j < 6; j++) s += sH[t * 6 + j];

    sSuf[t] = s;
    __syncthreads();
    unsigned rv = sSuf[511 - t];
    unsigned x = rv;
    #pragma unroll
    for (int d = 1; d < 32; d <<= 1) {
        unsigned y = __shfl_up_sync(0xFFFFFFFFu, x, d);
        if (lane >= d) x += y;
    }
    if (lane == 31) sWSum[wp] = x;
    __syncthreads();
    if (wp == 0) {
        unsigned ws = (lane < 16) ? sWSum[lane] : 0u;
        #pragma unroll
        for (int d = 1; d < 16; d <<= 1) {
            unsigned y = __shfl_up_sync(0xFFFFFFFFu, ws, d);
            if (lane >= d) ws += y;
        }
        if (lane < 16) sWSum[lane] = ws;
    }
    __syncthreads();
    unsigned inc = x + (wp > 0 ? sWSum[wp - 1] : 0u);
    __syncthreads();
    sSuf[511 - t] = inc;
    if (t == 0) { sSuf[512] = 0u; sChunk = -1; }
    __syncthreads();

    unsigned total = sSuf[0];
    if (total > KTOP) {
        if (sSuf[t] >= KTOP && sSuf[t + 1] < KTOP) sChunk = t;
    }
    __syncthreads();

    if (t == 0) {
        unsigned thr, cnt;
        if (total <= KTOP) {
            thr = KBASE + 1u; cnt = total;
        } else {
            int ts = sChunk;
            unsigned cum2 = sSuf[ts + 1];
            int bin = ts * 6 + 5;
            unsigned hv;
            for (;; bin--) { hv = sH[bin]; if (cum2 + hv >= KTOP) break; cum2 += hv; }
            cnt = cum2 + hv;
            while (cnt > CAND) { cnt -= sH[bin]; bin++; }   // safety, never expected
            thr = KBASE + ((unsigned)bin << KSHIFT);
        }
        sThr = thr;
        sCtr = 0;
    }
    for (int i = t; i < CAND; i += 512) sCand[i] = 0ull;
    __syncthreads();
    unsigned thr = sThr;

    const unsigned* keys = g_key + off;
    for (int i = t; i < N; i += 512) {
        unsigned k = keys[i];
        if (k >= thr) {
            unsigned pos = atomicAdd(&sCtr, 1u);
            if (pos < CAND)
                sCand[pos] = ((unsigned long long)k << 32) | (unsigned)(~(unsigned)i);
        }
    }
    __syncthreads();

    // bitonic sort 1024, descending; each thread handles one pair
    for (int kk = 2; kk <= CAND; kk <<= 1) {
        for (int j = kk >> 1; j > 0; j >>= 1) {
            int i = ((t & ~(j - 1)) << 1) | (t & (j - 1));
            int ix = i | j;
            unsigned long long a = sCand[i], bb = sCand[ix];
            bool up = (i & kk) == 0;
            if ((a < bb) == up) { sCand[i] = bb; sCand[ix] = a; }
            __syncthreads();
        }
    }

    unsigned long long e = sCand[t];
    bool vv = (e != 0ull);
    int slot = bl * KTOP + t;
    float4 bx = make_float4(0.f, 0.f, 0.f, 0.f);
    float sc = 0.f; int lb = 0;
    if (vv) {
        int i = (int)(~(unsigned)e);
        bx = g_box[off + i]; sc = g_sc[off + i]; lb = g_lab[off + i];
    }
    g_tbox[slot] = bx; g_tsc[slot] = sc; g_tlab[slot] = lb;
    unsigned wball = __ballot_sync(0xFFFFFFFFu, vv);
    if (lane == 0) g_tval[bl * 16 + wp] = wball;
}

// upper-triangle IoU bitmask: row r holds cols j>r only
__global__ void __launch_bounds__(512) mask_kernel() {
    __shared__ float4 sB[KTOP];
    int bl = blockIdx.x >> 4, tile = blockIdx.x & 15;
    int t = threadIdx.x, lane = t & 31, wp = t >> 5;
    sB[t] = g_tbox[bl * KTOP + t];
    __syncthreads();

    int r0 = tile * 32 + wp * 2;
    for (int rr = r0; rr < r0 + 2; rr++) {
        float4 br = sB[rr];
        float ar = __fmul_rn(__fsub_rn(br.z, br.x), __fsub_rn(br.w, br.y));
        for (int c = tile; c < 16; c++) {
            float4 bj = sB[c * 32 + lane];
            float ltx = fmaxf(br.x, bj.x), lty = fmaxf(br.y, bj.y);
            float rbx = fminf(br.z, bj.z), rby = fminf(br.w, bj.w);
            float wx = fmaxf(__fsub_rn(rbx, ltx), 0.f);
            float wy = fmaxf(__fsub_rn(rby, lty), 0.f);
            float inter = __fmul_rn(wx, wy);
            unsigned wd = 0u;
            if (__any_sync(0xFFFFFFFFu, inter > 0.f)) {
                float aj = __fmul_rn(__fsub_rn(bj.z, bj.x), __fsub_rn(bj.w, bj.y));
                float den = __fadd_rn(__fsub_rn(__fadd_rn(ar, aj), inter), 1e-9f);
                bool bit = __fdiv_rn(inter, den) > 0.5f;
                wd = __ballot_sync(0xFFFFFFFFu, bit);
            }
            if (c == tile) {  // keep only cols j > rr
                int rb = rr & 31;
                wd &= (rb == 31) ? 0u : (0xFFFFFFFFu << (rb + 1));
            }
            if (lane == 0) g_mask[(bl * KTOP + rr) * 16 + c] = wd;
        }
    }
}

// warp-cooperative greedy NMS scan
__global__ void __launch_bounds__(512) scan_kernel(float* __restrict__ out) {
    __shared__ unsigned sM[KTOP * 16];
    __shared__ unsigned sKeep[16];
    int bl = blockIdx.x, t = threadIdx.x;
    const unsigned* gm = g_mask + bl * KTOP * 16;
    for (int i = t; i < KTOP * 16; i += 512) sM[i] = gm[i];
    __syncthreads();

    if (t < 32) {
        unsigned sup = 0u;   // lane j (<16) owns suppression word j
        #pragma unroll 1
        for (int w = 0; w < 16; w++) {
            unsigned supw = __shfl_sync(0xFFFFFFFFu, sup, w);
            unsigned vw = g_tval[bl * 16 + w];
            unsigned intra = sM[(w * 32 + t) * 16 + w];   // lane t: row (w*32+t)'s intra word
            unsigned alive = vw & ~supw;
            unsigned kw = 0u;
            while (alive) {
                int r = __ffs(alive) - 1;
                kw |= 1u << r;
                unsigned mr = __shfl_sync(0xFFFFFFFFu, intra, r);
                alive &= ~(mr | (1u << r));
            }
            // lane-parallel cross-group OR of kept rows' masks
            unsigned kws = kw;
            while (kws) {
                int r = __ffs(kws) - 1;
                kws &= kws - 1;
                if (t < 16) sup |= sM[(w * 32 + r) * 16 + t];
            }
            if (t == 0) sKeep[w] = kw;
        }
    }
    __syncthreads();

    bool kp = (sKeep[t >> 5] >> (t & 31)) & 1u;
    int slot = bl * KTOP + t;
    float4 bx = kp ? g_tbox[slot] : make_float4(0.f, 0.f, 0.f, 0.f);
    ((float4*)out)[slot] = bx;
    out[32768 + slot] = kp ? g_tsc[slot] : 0.f;
    out[40960 + slot] = kp ? (float)(g_tlab[slot] + 1) : 0.f;
    out[49152 + slot] = kp ? 1.f : 0.f;
}

extern "C" void kernel_launch(void* const* d_in, const int* in_sizes, int n_in,
                              void* d_out, int out_size) {
    dim3 gdec(192, 4, 4);
    decode_kernel<<<gdec, 256>>>(
        (const float*)d_in[0],  (const float*)d_in[1],  (const float*)d_in[2],
        (const float*)d_in[3],  (const float*)d_in[4],  (const float*)d_in[5],
        (const float*)d_in[6],  (const float*)d_in[7],  (const float*)d_in[8],
        (const float*)d_in[9],  (const float*)d_in[10], (const float*)d_in[11]);
    topk_kernel<<<16, 512>>>();
    mask_kernel<<<256, 512>>>();
    scan_kernel<<<16, 512>>>((float*)d_out);
}

// round 6
// speedup vs baseline: 1.4467x; 1.4467x over previous
#include <cuda_runtime.h>

#define KTOP 512
#define NBL 16
#define NANCH 65280
#define NB2 3072          // fine bins (2868 used)
#define CAND 1024
#define KBASE 0xBE19999Au // fkey(0.15f)
#define KSHIFT 13

__device__ unsigned g_key[4 * NANCH];
__device__ float4   g_box[4 * NANCH];
__device__ float    g_sc [4 * NANCH];
__device__ int      g_lab[4 * NANCH];
__device__ unsigned g_hist[NBL * NB2];
__device__ float4   g_tbox[NBL * KTOP];
__device__ float    g_tsc [NBL * KTOP];
__device__ int      g_tlab[NBL * KTOP];
__device__ unsigned g_tval[NBL * 16];
__device__ unsigned g_mask[NBL * KTOP * 16];

__constant__ int   c_HW[4]  = {16384, 4096, 1024, 256};
__constant__ int   c_lg[4]  = {14, 12, 10, 8};
__constant__ int   c_N[4]   = {49152, 12288, 3072, 768};
__constant__ int   c_off[4] = {0, 49152, 61440, 64512};
__constant__ float c_fs[4]  = {0.25f, 0.125f, 0.0625f, 0.03125f};
__constant__ float c_wsc[4] = {0.8f, 0.9f, 1.0f, 1.1f};
__constant__ float c_hsc[4] = {1.0f, 1.2f, 1.4f, 1.6f};
__constant__ float c_ew[4]  = {0.2f, 0.3f, 0.4f, 0.5f};
__constant__ float c_eh[4]  = {0.4f, 0.6f, 0.8f, 1.0f};
__constant__ float c_pwl[4] = {0.008f, 0.016f, 0.024f, 0.032f};
__constant__ float c_pwh[4] = {0.054f, 0.072f, 0.09f, 0.108f};
__constant__ float c_phl[4] = {0.008f, 0.016f, 0.024f, 0.032f};
__constant__ float c_phh[4] = {0.072f, 0.096f, 0.12f, 0.144f};
__constant__ float c_whl[4] = {0.005f, 0.01f, 0.015f, 0.02f};
__constant__ float c_whh[4] = {0.12f, 0.16f, 0.2f, 0.24f};

__device__ __forceinline__ unsigned fkey(float f) {
    unsigned u = __float_as_uint(f);
    return u ^ ((u >> 31) ? 0xFFFFFFFFu : 0x80000000u);
}

// XLA tanh: rational approximation, separate mul/add (no FMA contraction).
__device__ __forceinline__ float xla_tanh(float x) {
    float xc = fminf(fmaxf(x, -9.0f), 9.0f);
    float x2 = __fmul_rn(xc, xc);
    float p = -2.76076847742355e-16f;
    p = __fadd_rn(__fmul_rn(p, x2), 2.00018790482477e-13f);
    p = __fadd_rn(__fmul_rn(p, x2), -8.60467152213735e-11f);
    p = __fadd_rn(__fmul_rn(p, x2), 5.12229709037114e-08f);
    p = __fadd_rn(__fmul_rn(p, x2), 1.48572235717979e-05f);
    p = __fadd_rn(__fmul_rn(p, x2), 6.37261928875436e-04f);
    p = __fadd_rn(__fmul_rn(p, x2), 4.89352455891786e-03f);
    p = __fmul_rn(xc, p);
    float q = 1.19825839466702e-06f;
    q = __fadd_rn(__fmul_rn(q, x2), 1.18534705686654e-04f);
    q = __fadd_rn(__fmul_rn(q, x2), 2.26843463243900e-03f);
    q = __fadd_rn(__fmul_rn(q, x2), 4.89352518554385e-03f);
    float r = __fdiv_rn(p, q);
    return (fabsf(x) < 0.0004f) ? x : r;
}
__device__ __forceinline__ float xla_sigmoid(float x) {
    return __fadd_rn(0.5f, __fmul_rn(0.5f, xla_tanh(__fmul_rn(0.5f, x))));
}
__device__ __forceinline__ float clip01(float x) { return fminf(fmaxf(x, 0.0f), 1.0f); }

__global__ void __launch_bounds__(256) decode_kernel(
    const float* __restrict__ cls0, const float* __restrict__ box0, const float* __restrict__ anc0,
    const float* __restrict__ cls1, const float* __restrict__ box1, const float* __restrict__ anc1,
    const float* __restrict__ cls2, const float* __restrict__ box2, const float* __restrict__ anc2,
    const float* __restrict__ cls3, const float* __restrict__ box3, const float* __restrict__ anc3)
{
    int l = blockIdx.z, b = blockIdx.y;
    int i = blockIdx.x * 256 + threadIdx.x;
    if (i >= c_N[l]) return;
    int HW = c_HW[l], lg = c_lg[l];
    const float* cls = (l == 0) ? cls0 : (l == 1) ? cls1 : (l == 2) ? cls2 : cls3;
    const float* box = (l == 0) ? box0 : (l == 1) ? box1 : (l == 2) ? box2 : box3;
    const float* anc = (l == 0) ? anc0 : (l == 1) ? anc1 : (l == 2) ? anc2 : anc3;

    int a = i >> lg, p = i & (HW - 1);
    const float* cb = cls + (size_t)((b * 3 + a) * 3) * HW + p;
    float s0 = xla_sigmoid(cb[0]);
    float s1 = xla_sigmoid(cb[HW]);
    float s2 = xla_sigmoid(cb[2 * HW]);
    float ms = s0; int lb = 0;
    if (s1 > ms) { ms = s1; lb = 1; }
    if (s2 > ms) { ms = s2; lb = 2; }

    const float* db = box + (size_t)((b * 3 + a) * 4) * HW + p;
    float d0 = db[0], d1 = db[HW], d2 = db[2 * HW], d3 = db[3 * HW];

    float4 A = ((const float4*)anc)[i];
    const float inv = 0.001953125f;
    float aw  = __fmul_rn(__fsub_rn(A.z, A.x), inv);
    float ah  = __fmul_rn(__fsub_rn(A.w, A.y), inv);
    float acx = __fmul_rn(__fmul_rn(__fadd_rn(A.x, A.z), 0.5f), inv);
    float acy = __fmul_rn(__fmul_rn(__fadd_rn(A.y, A.w), 0.5f), inv);

    float dx = __fmul_rn(__fmul_rn(fminf(fmaxf(__fmul_rn(d0, 0.2f), -1.0f), 1.0f), c_fs[l]), aw);
    float dy = __fmul_rn(__fmul_rn(fminf(fmaxf(__fmul_rn(d1, 0.2f), -1.0f), 1.0f), c_fs[l]), ah);
    float cx = clip01(__fadd_rn(acx, dx));
    float cy = clip01(__fadd_rn(acy, dy));
    float dw = fminf(fmaxf(__fmul_rn(d2, 0.2f), -2.0f), 2.0f);
    float dh = fminf(fmaxf(__fmul_rn(d3, 0.2f), -2.0f), 2.0f);
    float pw = fminf(fmaxf(__fmul_rn(__fmul_rn(aw, c_wsc[l]), expf(__fmul_rn(dw, c_ew[l]))), c_pwl[l]), c_pwh[l]);
    float ph = fminf(fmaxf(__fmul_rn(__fmul_rn(ah, c_hsc[l]), expf(__fmul_rn(dh, c_eh[l]))), c_phl[l]), c_phh[l]);

    float x0 = clip01(__fsub_rn(cx, __fmul_rn(0.5f, pw)));
    float y0 = clip01(__fsub_rn(cy, __fmul_rn(0.5f, ph)));
    float x1 = clip01(__fadd_rn(cx, __fmul_rn(0.5f, pw)));
    float y1 = clip01(__fadd_rn(cy, __fmul_rn(0.5f, ph)));
    float w = __fsub_rn(x1, x0);
    float h = __fsub_rn(y1, y0);

    bool valid = (ms > 0.15f) && (w > c_whl[l]) && (h > c_whl[l]) && (w < c_whh[l]) && (h < c_whh[l]);
    int off = b * NANCH + c_off[l] + i;
    g_box[off] = make_float4(x0, y0, x1, y1);
    g_sc[off]  = ms;
    g_lab[off] = lb;
    unsigned key = valid ? fkey(ms) : 0u;
    g_key[off] = key;
    if (valid) atomicAdd(&g_hist[(b * 4 + l) * NB2 + ((key - KBASE) >> KSHIFT)], 1u);
}

__global__ void __launch_bounds__(512) topk_kernel() {
    __shared__ unsigned sH[NB2];
    __shared__ unsigned sSuf[513];
    __shared__ unsigned sWSum[16];
    __shared__ unsigned long long sCand[CAND];
    __shared__ unsigned sThr, sCtr;
    __shared__ int sChunk;
    int bl = blockIdx.x, b = bl >> 2, l = bl & 3;
    int t = threadIdx.x, lane = t & 31, wp = t >> 5;
    int N = c_N[l];
    int off = b * NANCH + c_off[l];
    unsigned* hist = g_hist + bl * NB2;

    for (int i = t; i < NB2; i += 512) { sH[i] = hist[i]; }
    __syncthreads();
    for (int i = t; i < NB2; i += 512) hist[i] = 0u;

    unsigned s = 0;
    #pragma unroll
    for (int j = 0; j < 6; j++) s += sH[t * 6 + j];

    sSuf[t] = s;
    __syncthreads();
    unsigned rv = sSuf[511 - t];
    unsigned x = rv;
    #pragma unroll
    for (int d = 1; d < 32; d <<= 1) {
        unsigned y = __shfl_up_sync(0xFFFFFFFFu, x, d);
        if (lane >= d) x += y;
    }
    if (lane == 31) sWSum[wp] = x;
    __syncthreads();
    if (wp == 0) {
        unsigned ws = (lane < 16) ? sWSum[lane] : 0u;
        #pragma unroll
        for (int d = 1; d < 16; d <<= 1) {
            unsigned y = __shfl_up_sync(0xFFFFFFFFu, ws, d);
            if (lane >= d) ws += y;
        }
        if (lane < 16) sWSum[lane] = ws;
    }
    __syncthreads();
    unsigned inc = x + (wp > 0 ? sWSum[wp - 1] : 0u);
    __syncthreads();
    sSuf[511 - t] = inc;
    if (t == 0) { sSuf[512] = 0u; sChunk = -1; }
    __syncthreads();

    unsigned total = sSuf[0];
    if (total > KTOP) {
        if (sSuf[t] >= KTOP && sSuf[t + 1] < KTOP) sChunk = t;
    }
    __syncthreads();

    if (t == 0) {
        unsigned thr, cnt;
        if (total <= KTOP) {
            thr = KBASE + 1u; cnt = total;
        } else {
            int ts = sChunk;
            unsigned cum2 = sSuf[ts + 1];
            int bin = ts * 6 + 5;
            unsigned hv;
            for (;; bin--) { hv = sH[bin]; if (cum2 + hv >= KTOP) break; cum2 += hv; }
            cnt = cum2 + hv;
            while (cnt > CAND) { cnt -= sH[bin]; bin++; }   // safety, never expected
            thr = KBASE + ((unsigned)bin << KSHIFT);
        }
        sThr = thr;
        sCtr = 0;
    }
    for (int i = t; i < CAND; i += 512) sCand[i] = 0ull;
    __syncthreads();
    unsigned thr = sThr;

    const unsigned* keys = g_key + off;
    for (int i = t; i < N; i += 512) {
        unsigned k = keys[i];
        if (k >= thr) {
            unsigned pos = atomicAdd(&sCtr, 1u);
            if (pos < CAND)
                sCand[pos] = ((unsigned long long)k << 32) | (unsigned)(~(unsigned)i);
        }
    }
    __syncthreads();

    for (int kk = 2; kk <= CAND; kk <<= 1) {
        for (int j = kk >> 1; j > 0; j >>= 1) {
            int i = ((t & ~(j - 1)) << 1) | (t & (j - 1));
            int ix = i | j;
            unsigned long long a = sCand[i], bb = sCand[ix];
            bool up = (i & kk) == 0;
            if ((a < bb) == up) { sCand[i] = bb; sCand[ix] = a; }
            __syncthreads();
        }
    }

    unsigned long long e = sCand[t];
    bool vv = (e != 0ull);
    int slot = bl * KTOP + t;
    float4 bx = make_float4(0.f, 0.f, 0.f, 0.f);
    float sc = 0.f; int lb = 0;
    if (vv) {
        int i = (int)(~(unsigned)e);
        bx = g_box[off + i]; sc = g_sc[off + i]; lb = g_lab[off + i];
    }
    g_tbox[slot] = bx; g_tsc[slot] = sc; g_tlab[slot] = lb;
    unsigned wball = __ballot_sync(0xFFFFFFFFu, vv);
    if (lane == 0) g_tval[bl * 16 + wp] = wball;
}

// upper-triangle IoU bitmask: row r holds cols j>r only
__global__ void __launch_bounds__(512) mask_kernel() {
    __shared__ float4 sB[KTOP];
    int bl = blockIdx.x >> 4, tile = blockIdx.x & 15;
    int t = threadIdx.x, lane = t & 31, wp = t >> 5;
    sB[t] = g_tbox[bl * KTOP + t];
    __syncthreads();

    int r0 = tile * 32 + wp * 2;
    for (int rr = r0; rr < r0 + 2; rr++) {
        float4 br = sB[rr];
        float ar = __fmul_rn(__fsub_rn(br.z, br.x), __fsub_rn(br.w, br.y));
        for (int c = tile; c < 16; c++) {
            float4 bj = sB[c * 32 + lane];
            float ltx = fmaxf(br.x, bj.x), lty = fmaxf(br.y, bj.y);
            float rbx = fminf(br.z, bj.z), rby = fminf(br.w, bj.w);
            float wx = fmaxf(__fsub_rn(rbx, ltx), 0.f);
            float wy = fmaxf(__fsub_rn(rby, lty), 0.f);
            float inter = __fmul_rn(wx, wy);
            unsigned wd = 0u;
            if (__any_sync(0xFFFFFFFFu, inter > 0.f)) {
                float aj = __fmul_rn(__fsub_rn(bj.z, bj.x), __fsub_rn(bj.w, bj.y));
                float den = __fadd_rn(__fsub_rn(__fadd_rn(ar, aj), inter), 1e-9f);
                bool bit = __fdiv_rn(inter, den) > 0.5f;
                wd = __ballot_sync(0xFFFFFFFFu, bit);
            }
            if (c == tile) {  // keep only cols j > rr
                int rb = rr & 31;
                wd &= (rb == 31) ? 0u : (0xFFFFFFFFu << (rb + 1));
            }
            if (lane == 0) g_mask[(bl * KTOP + rr) * 16 + c] = wd;
        }
    }
}

// sparsity-aware warp-cooperative greedy NMS scan
__global__ void __launch_bounds__(512) scan_kernel(float* __restrict__ out) {
    __shared__ unsigned sM[KTOP * 16];
    __shared__ unsigned sKeep[16];
    __shared__ unsigned sVal[16];
    __shared__ unsigned sColP[16 * 16];
    __shared__ unsigned sCol[16];
    int bl = blockIdx.x, t = threadIdx.x, lane = t & 31, wp = t >> 5;
    const unsigned* gm = g_mask + bl * KTOP * 16;

    // load masks; thread t only ever touches word index (t & 15) -> free colocc partials
    unsigned myor = 0u;
    for (int i = t; i < KTOP * 16; i += 512) { unsigned v = gm[i]; sM[i] = v; myor |= v; }
    myor |= __shfl_xor_sync(0xFFFFFFFFu, myor, 16);
    if (lane < 16) sColP[wp * 16 + lane] = myor;
    if (t < 16) sVal[t] = g_tval[bl * 16 + t];
    __syncthreads();
    if (t < 16) {
        unsigned c = 0u;
        #pragma unroll
        for (int k = 0; k < 16; k++) c |= sColP[k * 16 + t];
        sCol[t] = c;   // bit j of word w: some earlier box overlaps box w*32+j
    }
    __syncthreads();

    if (t < 32) {
        int j = t & 15;
        unsigned sup = 0u;   // lane t: suppression word (t&15); lanes 16-31 mirror
        #pragma unroll 1
        for (int w = 0; w < 16; w++) {
            unsigned vw = sVal[w];
            unsigned kw = 0u;
            if (vw) {
                unsigned colw = sCol[w];
                unsigned intra = sM[(w * 32 + lane) * 16 + w];
                unsigned autok = vw & ~colw;      // nobody can suppress these: kept
                kw = autok;
                // fold autokeep rows into suppression (lane-parallel, independent LDS)
                unsigned rows = autok;
                while (rows) {
                    int r = __ffs(rows) - 1; rows &= rows - 1;
                    sup |= sM[(w * 32 + r) * 16 + j];
                }
                unsigned supw = __shfl_sync(0xFFFFFFFFu, sup, w);
                // sequential chain only over column-occupied, unsuppressed boxes
                unsigned chain = vw & colw & ~supw;
                while (chain) {
                    int r = __ffs(chain) - 1;
                    kw |= 1u << r;
                    unsigned mr = __shfl_sync(0xFFFFFFFFu, intra, r);
                    chain &= ~(mr | (1u << r));
                    sup |= sM[(w * 32 + r) * 16 + j];
                }
            }
            if (t == 0) sKeep[w] = kw;
        }
    }
    __syncthreads();

    bool kp = (sKeep[t >> 5] >> (t & 31)) & 1u;
    int slot = bl * KTOP + t;
    float4 bx = kp ? g_tbox[slot] : make_float4(0.f, 0.f, 0.f, 0.f);
    ((float4*)out)[slot] = bx;
    out[32768 + slot] = kp ? g_tsc[slot] : 0.f;
    out[40960 + slot] = kp ? (float)(g_tlab[slot] + 1) : 0.f;
    out[49152 + slot] = kp ? 1.f : 0.f;
}

extern "C" void kernel_launch(void* const* d_in, const int* in_sizes, int n_in,
                              void* d_out, int out_size) {
    dim3 gdec(192, 4, 4);
    decode_kernel<<<gdec, 256>>>(
        (const float*)d_in[0],  (const float*)d_in[1],  (const float*)d_in[2],
        (const float*)d_in[3],  (const float*)d_in[4],  (const float*)d_in[5],
        (const float*)d_in[6],  (const float*)d_in[7],  (const float*)d_in[8],
        (const float*)d_in[9],  (const float*)d_in[10], (const float*)d_in[11]);
    topk_kernel<<<16, 512>>>();
    mask_kernel<<<256, 512>>>();
    scan_kernel<<<16, 512>>>((float*)d_out);
}

// round 7
// speedup vs baseline: 2.2996x; 1.5895x over previous
#include <cuda_runtime.h>

#define KTOP 512
#define NBL 16
#define NANCH 65280
#define NB2 3072          // fine bins (2868 used)
#define CAND 1024
#define KBASE 0xBE19999Au // fkey(0.15f)
#define KSHIFT 13

__device__ unsigned g_key[4 * NANCH];
__device__ float4   g_box[4 * NANCH];
__device__ float    g_sc [4 * NANCH];
__device__ int      g_lab[4 * NANCH];
__device__ unsigned g_hist[NBL * NB2];
__device__ float4   g_tbox[NBL * KTOP];
__device__ float    g_tsc [NBL * KTOP];
__device__ int      g_tlab[NBL * KTOP];
__device__ unsigned g_tval[NBL * 16];
__device__ unsigned g_mask[NBL * KTOP * 16];

__constant__ int   c_HW[4]  = {16384, 4096, 1024, 256};
__constant__ int   c_lg[4]  = {14, 12, 10, 8};
__constant__ int   c_N[4]   = {49152, 12288, 3072, 768};
__constant__ int   c_off[4] = {0, 49152, 61440, 64512};
__constant__ float c_fs[4]  = {0.25f, 0.125f, 0.0625f, 0.03125f};
__constant__ float c_wsc[4] = {0.8f, 0.9f, 1.0f, 1.1f};
__constant__ float c_hsc[4] = {1.0f, 1.2f, 1.4f, 1.6f};
__constant__ float c_ew[4]  = {0.2f, 0.3f, 0.4f, 0.5f};
__constant__ float c_eh[4]  = {0.4f, 0.6f, 0.8f, 1.0f};
__constant__ float c_pwl[4] = {0.008f, 0.016f, 0.024f, 0.032f};
__constant__ float c_pwh[4] = {0.054f, 0.072f, 0.09f, 0.108f};
__constant__ float c_phl[4] = {0.008f, 0.016f, 0.024f, 0.032f};
__constant__ float c_phh[4] = {0.072f, 0.096f, 0.12f, 0.144f};
__constant__ float c_whl[4] = {0.005f, 0.01f, 0.015f, 0.02f};
__constant__ float c_whh[4] = {0.12f, 0.16f, 0.2f, 0.24f};

__device__ __forceinline__ unsigned fkey(float f) {
    unsigned u = __float_as_uint(f);
    return u ^ ((u >> 31) ? 0xFFFFFFFFu : 0x80000000u);
}

// XLA tanh: rational approximation, separate mul/add (no FMA contraction).
__device__ __forceinline__ float xla_tanh(float x) {
    float xc = fminf(fmaxf(x, -9.0f), 9.0f);
    float x2 = __fmul_rn(xc, xc);
    float p = -2.76076847742355e-16f;
    p = __fadd_rn(__fmul_rn(p, x2), 2.00018790482477e-13f);
    p = __fadd_rn(__fmul_rn(p, x2), -8.60467152213735e-11f);
    p = __fadd_rn(__fmul_rn(p, x2), 5.12229709037114e-08f);
    p = __fadd_rn(__fmul_rn(p, x2), 1.48572235717979e-05f);
    p = __fadd_rn(__fmul_rn(p, x2), 6.37261928875436e-04f);
    p = __fadd_rn(__fmul_rn(p, x2), 4.89352455891786e-03f);
    p = __fmul_rn(xc, p);
    float q = 1.19825839466702e-06f;
    q = __fadd_rn(__fmul_rn(q, x2), 1.18534705686654e-04f);
    q = __fadd_rn(__fmul_rn(q, x2), 2.26843463243900e-03f);
    q = __fadd_rn(__fmul_rn(q, x2), 4.89352518554385e-03f);
    float r = __fdiv_rn(p, q);
    return (fabsf(x) < 0.0004f) ? x : r;
}
__device__ __forceinline__ float xla_sigmoid(float x) {
    return __fadd_rn(0.5f, __fmul_rn(0.5f, xla_tanh(__fmul_rn(0.5f, x))));
}
__device__ __forceinline__ float clip01(float x) { return fminf(fmaxf(x, 0.0f), 1.0f); }

__global__ void __launch_bounds__(256) decode_kernel(
    const float* __restrict__ cls0, const float* __restrict__ box0, const float* __restrict__ anc0,
    const float* __restrict__ cls1, const float* __restrict__ box1, const float* __restrict__ anc1,
    const float* __restrict__ cls2, const float* __restrict__ box2, const float* __restrict__ anc2,
    const float* __restrict__ cls3, const float* __restrict__ box3, const float* __restrict__ anc3)
{
    int l = blockIdx.z, b = blockIdx.y;
    int i = blockIdx.x * 256 + threadIdx.x;
    if (i >= c_N[l]) return;
    int HW = c_HW[l], lg = c_lg[l];
    const float* cls = (l == 0) ? cls0 : (l == 1) ? cls1 : (l == 2) ? cls2 : cls3;
    const float* box = (l == 0) ? box0 : (l == 1) ? box1 : (l == 2) ? box2 : box3;
    const float* anc = (l == 0) ? anc0 : (l == 1) ? anc1 : (l == 2) ? anc2 : anc3;

    int a = i >> lg, p = i & (HW - 1);
    const float* cb = cls + (size_t)((b * 3 + a) * 3) * HW + p;
    float s0 = xla_sigmoid(cb[0]);
    float s1 = xla_sigmoid(cb[HW]);
    float s2 = xla_sigmoid(cb[2 * HW]);
    float ms = s0; int lb = 0;
    if (s1 > ms) { ms = s1; lb = 1; }
    if (s2 > ms) { ms = s2; lb = 2; }

    const float* db = box + (size_t)((b * 3 + a) * 4) * HW + p;
    float d0 = db[0], d1 = db[HW], d2 = db[2 * HW], d3 = db[3 * HW];

    float4 A = ((const float4*)anc)[i];
    const float inv = 0.001953125f;
    float aw  = __fmul_rn(__fsub_rn(A.z, A.x), inv);
    float ah  = __fmul_rn(__fsub_rn(A.w, A.y), inv);
    float acx = __fmul_rn(__fmul_rn(__fadd_rn(A.x, A.z), 0.5f), inv);
    float acy = __fmul_rn(__fmul_rn(__fadd_rn(A.y, A.w), 0.5f), inv);

    float dx = __fmul_rn(__fmul_rn(fminf(fmaxf(__fmul_rn(d0, 0.2f), -1.0f), 1.0f), c_fs[l]), aw);
    float dy = __fmul_rn(__fmul_rn(fminf(fmaxf(__fmul_rn(d1, 0.2f), -1.0f), 1.0f), c_fs[l]), ah);
    float cx = clip01(__fadd_rn(acx, dx));
    float cy = clip01(__fadd_rn(acy, dy));
    float dw = fminf(fmaxf(__fmul_rn(d2, 0.2f), -2.0f), 2.0f);
    float dh = fminf(fmaxf(__fmul_rn(d3, 0.2f), -2.0f), 2.0f);
    float pw = fminf(fmaxf(__fmul_rn(__fmul_rn(aw, c_wsc[l]), expf(__fmul_rn(dw, c_ew[l]))), c_pwl[l]), c_pwh[l]);
    float ph = fminf(fmaxf(__fmul_rn(__fmul_rn(ah, c_hsc[l]), expf(__fmul_rn(dh, c_eh[l]))), c_phl[l]), c_phh[l]);

    float x0 = clip01(__fsub_rn(cx, __fmul_rn(0.5f, pw)));
    float y0 = clip01(__fsub_rn(cy, __fmul_rn(0.5f, ph)));
    float x1 = clip01(__fadd_rn(cx, __fmul_rn(0.5f, pw)));
    float y1 = clip01(__fadd_rn(cy, __fmul_rn(0.5f, ph)));
    float w = __fsub_rn(x1, x0);
    float h = __fsub_rn(y1, y0);

    bool valid = (ms > 0.15f) && (w > c_whl[l]) && (h > c_whl[l]) && (w < c_whh[l]) && (h < c_whh[l]);
    int off = b * NANCH + c_off[l] + i;
    g_box[off] = make_float4(x0, y0, x1, y1);
    g_sc[off]  = ms;
    g_lab[off] = lb;
    unsigned key = valid ? fkey(ms) : 0u;
    g_key[off] = key;
    if (valid) atomicAdd(&g_hist[(b * 4 + l) * NB2 + ((key - KBASE) >> KSHIFT)], 1u);
}

__global__ void __launch_bounds__(512) topk_kernel() {
    __shared__ unsigned sH[NB2];
    __shared__ unsigned sSuf[513];
    __shared__ unsigned sWSum[16];
    __shared__ unsigned long long sCand[CAND];
    __shared__ unsigned sThr, sCtr;
    __shared__ int sChunk;
    int bl = blockIdx.x, b = bl >> 2, l = bl & 3;
    int t = threadIdx.x, lane = t & 31, wp = t >> 5;
    int N = c_N[l];
    int off = b * NANCH + c_off[l];
    unsigned* hist = g_hist + bl * NB2;

    for (int i = t; i < NB2; i += 512) { sH[i] = hist[i]; }
    __syncthreads();
    for (int i = t; i < NB2; i += 512) hist[i] = 0u;

    unsigned s = 0;
    #pragma unroll
    for (int j = 0; j < 6; j++) s += sH[t * 6 + j];

    sSuf[t] = s;
    __syncthreads();
    unsigned rv = sSuf[511 - t];
    unsigned x = rv;
    #pragma unroll
    for (int d = 1; d < 32; d <<= 1) {
        unsigned y = __shfl_up_sync(0xFFFFFFFFu, x, d);
        if (lane >= d) x += y;
    }
    if (lane == 31) sWSum[wp] = x;
    __syncthreads();
    if (wp == 0) {
        unsigned ws = (lane < 16) ? sWSum[lane] : 0u;
        #pragma unroll
        for (int d = 1; d < 16; d <<= 1) {
            unsigned y = __shfl_up_sync(0xFFFFFFFFu, ws, d);
            if (lane >= d) ws += y;
        }
        if (lane < 16) sWSum[lane] = ws;
    }
    __syncthreads();
    unsigned inc = x + (wp > 0 ? sWSum[wp - 1] : 0u);
    __syncthreads();
    sSuf[511 - t] = inc;
    if (t == 0) { sSuf[512] = 0u; sChunk = -1; }
    __syncthreads();

    unsigned total = sSuf[0];
    if (total > KTOP) {
        if (sSuf[t] >= KTOP && sSuf[t + 1] < KTOP) sChunk = t;
    }
    __syncthreads();

    if (t == 0) {
        unsigned thr, cnt;
        if (total <= KTOP) {
            thr = KBASE + 1u; cnt = total;
        } else {
            int ts = sChunk;
            unsigned cum2 = sSuf[ts + 1];
            int bin = ts * 6 + 5;
            unsigned hv;
            for (;; bin--) { hv = sH[bin]; if (cum2 + hv >= KTOP) break; cum2 += hv; }
            cnt = cum2 + hv;
            while (cnt > CAND) { cnt -= sH[bin]; bin++; }   // safety, never expected
            thr = KBASE + ((unsigned)bin << KSHIFT);
        }
        sThr = thr;
        sCtr = 0;
    }
    for (int i = t; i < CAND; i += 512) sCand[i] = 0ull;
    __syncthreads();
    unsigned thr = sThr;

    const unsigned* keys = g_key + off;
    for (int i = t; i < N; i += 512) {
        unsigned k = keys[i];
        if (k >= thr) {
            unsigned pos = atomicAdd(&sCtr, 1u);
            if (pos < CAND)
                sCand[pos] = ((unsigned long long)k << 32) | (unsigned)(~(unsigned)i);
        }
    }
    __syncthreads();

    for (int kk = 2; kk <= CAND; kk <<= 1) {
        for (int j = kk >> 1; j > 0; j >>= 1) {
            int i = ((t & ~(j - 1)) << 1) | (t & (j - 1));
            int ix = i | j;
            unsigned long long a = sCand[i], bb = sCand[ix];
            bool up = (i & kk) == 0;
            if ((a < bb) == up) { sCand[i] = bb; sCand[ix] = a; }
            __syncthreads();
        }
    }

    unsigned long long e = sCand[t];
    bool vv = (e != 0ull);
    int slot = bl * KTOP + t;
    float4 bx = make_float4(0.f, 0.f, 0.f, 0.f);
    float sc = 0.f; int lb = 0;
    if (vv) {
        int i = (int)(~(unsigned)e);
        bx = g_box[off + i]; sc = g_sc[off + i]; lb = g_lab[off + i];
    }
    g_tbox[slot] = bx; g_tsc[slot] = sc; g_tlab[slot] = lb;
    unsigned wball = __ballot_sync(0xFFFFFFFFu, vv);
    if (lane == 0) g_tval[bl * 16 + wp] = wball;
}

// LOWER-triangle IoU bitmask (transpose view): row i holds its SUPPRESSORS j<i.
// Row i's valid words are 0..(i>>5); word (i>>5) masked to bits j<(i&31).
__global__ void __launch_bounds__(512) mask_kernel() {
    __shared__ float4 sB[KTOP];
    int bl = blockIdx.x >> 4, tile = blockIdx.x & 15;
    int t = threadIdx.x, lane = t & 31, wp = t >> 5;
    sB[t] = g_tbox[bl * KTOP + t];
    __syncthreads();

    int r0 = tile * 32 + wp * 2;
    for (int rr = r0; rr < r0 + 2; rr++) {
        float4 br = sB[rr];
        float ar = __fmul_rn(__fsub_rn(br.z, br.x), __fsub_rn(br.w, br.y));
        for (int c = 0; c <= tile; c++) {
            float4 bj = sB[c * 32 + lane];
            float ltx = fmaxf(br.x, bj.x), lty = fmaxf(br.y, bj.y);
            float rbx = fminf(br.z, bj.z), rby = fminf(br.w, bj.w);
            float wx = fmaxf(__fsub_rn(rbx, ltx), 0.f);
            float wy = fmaxf(__fsub_rn(rby, lty), 0.f);
            float inter = __fmul_rn(wx, wy);
            unsigned wd = 0u;
            if (__any_sync(0xFFFFFFFFu, inter > 0.f)) {
                float aj = __fmul_rn(__fsub_rn(bj.z, bj.x), __fsub_rn(bj.w, bj.y));
                float den = __fadd_rn(__fsub_rn(__fadd_rn(ar, aj), inter), 1e-9f);
                bool bit = __fdiv_rn(inter, den) > 0.5f;
                wd = __ballot_sync(0xFFFFFFFFu, bit);
            }
            if (c == tile) {                 // keep only cols j < rr (strict)
                int rb = rr & 31;
                wd &= (1u << rb) - 1u;
            }
            if (lane == 0) g_mask[(bl * KTOP + rr) * 16 + c] = wd;
        }
    }
}

// Jacobi-fixpoint greedy NMS: converges to the exact greedy keep set.
__global__ void __launch_bounds__(512) scan_kernel(float* __restrict__ out) {
    __shared__ unsigned sK[16];
    int bl = blockIdx.x, t = threadIdx.x, lane = t & 31, wp = t >> 5;

    // load suppressor row (64B) into registers; zero statically-dead words
    const uint4* rowp = (const uint4*)(g_mask + (bl * KTOP + t) * 16);
    uint4 a0 = rowp[0], a1 = rowp[1], a2 = rowp[2], a3 = rowp[3];
    unsigned T[16];
    T[0]=a0.x; T[1]=a0.y; T[2]=a0.z; T[3]=a0.w;
    T[4]=a1.x; T[5]=a1.y; T[6]=a1.z; T[7]=a1.w;
    T[8]=a2.x; T[9]=a2.y; T[10]=a2.z; T[11]=a2.w;
    T[12]=a3.x; T[13]=a3.y; T[14]=a3.z; T[15]=a3.w;
    #pragma unroll
    for (int w = 0; w < 16; w++) if (w > wp) T[w] = 0u;

    unsigned vw = g_tval[bl * 16 + wp];
    bool vbit = (vw >> lane) & 1u;
    if (t < 16) sK[t] = g_tval[bl * 16 + t];   // k0 = valid
    __syncthreads();

    for (int it = 0; it < 512; it++) {
        unsigned sup = 0u;
        #pragma unroll
        for (int w = 0; w < 16; w++) sup |= T[w] & sK[w];
        bool nk = vbit && (sup == 0u);
        unsigned bal = __ballot_sync(0xFFFFFFFFu, nk);
        int ch = (lane == 0 && bal != sK[wp]) ? 1 : 0;
        int anyc = __syncthreads_or(ch);
        if (!anyc) break;
        if (lane == 0) sK[wp] = bal;
        __syncthreads();
    }

    bool kp = (sK[wp] >> lane) & 1u;
    int slot = bl * KTOP + t;
    float4 bx = kp ? g_tbox[slot] : make_float4(0.f, 0.f, 0.f, 0.f);
    ((float4*)out)[slot] = bx;
    out[32768 + slot] = kp ? g_tsc[slot] : 0.f;
    out[40960 + slot] = kp ? (float)(g_tlab[slot] + 1) : 0.f;
    out[49152 + slot] = kp ? 1.f : 0.f;
}

extern "C" void kernel_launch(void* const* d_in, const int* in_sizes, int n_in,
                              void* d_out, int out_size) {
    dim3 gdec(192, 4, 4);
    decode_kernel<<<gdec, 256>>>(
        (const float*)d_in[0],  (const float*)d_in[1],  (const float*)d_in[2],
        (const float*)d_in[3],  (const float*)d_in[4],  (const float*)d_in[5],
        (const float*)d_in[6],  (const float*)d_in[7],  (const float*)d_in[8],
        (const float*)d_in[9],  (const float*)d_in[10], (const float*)d_in[11]);
    topk_kernel<<<16, 512>>>();
    mask_kernel<<<256, 512>>>();
    scan_kernel<<<16, 512>>>((float*)d_out);
}